// round 13
// baseline (speedup 1.0000x reference)
#include <cuda_runtime.h>

// SSIM loss, pred/target [16,3,512,512] f32.
// Vertical-first separable 11-tap Gaussian, f32x2-packed:
//   stream A: (p, t) packed   stream B: (p*p, t*t) packed   stream C: p*t scalar
// Phase1: gmem -> smem (p,t) packed tile (74x42)
// Phase2: vertical conv, modulo-rotation register windows; A+B fused (shared
//         loads), tasks=(col,half) on tids 0-147; C on tids 160-233.
// Phase3: horizontal conv + SSIM map + deterministic block reduce
// Finalize folded into last-finished block (atomic counter, fixed-order sum).

#define TX   64
#define TY   32
#define LX   74
#define LY   42
#define SPW  75      // input tile row stride (u64)
#define CS   33      // v* column stride (32 rows + 1 pad)
#define GX   (512/TX)
#define GY   (512/TY)
#define GZ   48
#define NBLK (GX*GY*GZ)
#define NTOT 12582912.0

using u64 = unsigned long long;

__host__ __device__ constexpr float GWc(int k) {
    return (k == 0) ? 0.00102838f
         : (k == 1) ? 0.00759875f
         : (k == 2) ? 0.03600077f
         : (k == 3) ? 0.10936070f
         : (k == 4) ? 0.21300553f
         : (k == 5) ? 0.26601172f
         : (k == 6) ? 0.21300553f
         : (k == 7) ? 0.10936070f
         : (k == 8) ? 0.03600077f
         : (k == 9) ? 0.00759875f
         :            0.00102838f;
}

__device__ __forceinline__ u64 pack2(float lo, float hi) {
    u64 r; asm("mov.b64 %0, {%1,%2};" : "=l"(r) : "f"(lo), "f"(hi)); return r;
}
__device__ __forceinline__ void unpack2(u64 v, float& lo, float& hi) {
    asm("mov.b64 {%0,%1}, %2;" : "=f"(lo), "=f"(hi) : "l"(v));
}
__device__ __forceinline__ u64 fma2(u64 a, u64 b, u64 c) {
    u64 r; asm("fma.rn.f32x2 %0, %1, %2, %3;" : "=l"(r) : "l"(a), "l"(b), "l"(c)); return r;
}
__device__ __forceinline__ u64 mul2(u64 a, u64 b) {
    u64 r; asm("mul.rn.f32x2 %0, %1, %2;" : "=l"(r) : "l"(a), "l"(b)); return r;
}

__device__ float g_partials[NBLK];
__device__ unsigned int g_count = 0;

__global__ void __launch_bounds__(256, 2)
ssim_tile_kernel(const float* __restrict__ pred, const float* __restrict__ targ,
                 float* __restrict__ out)
{
    extern __shared__ char smem_raw[];
    u64*   spt  = (u64*)smem_raw;              // LY*SPW   (p,t) tile
    u64*   vA   = spt + LY * SPW;              // 74*CS    vpass (mu1v, mu2v) [col][row]
    u64*   vB   = vA + 74 * CS;                // 74*CS    vpass (p2v, t2v)   [col][row]
    float* vC   = (float*)(vB + 74 * CS);      // 74*CS    vpass ptv          [col][row]
    float* sred = vC + 74 * CS;                // 8 floats

    const int tid = threadIdx.x;
    const int x0 = blockIdx.x * TX;
    const int y0 = blockIdx.y * TY;
    const int z  = blockIdx.z;
    const float* pb = pred + z * (512 * 512);
    const float* tb = targ + z * (512 * 512);

    // ---- Phase 1: load tile with halo, interleave (p,t) ----
    for (int i = tid; i < LY * LX; i += 256) {
        int r = i / LX;
        int c = i - r * LX;
        int gy = y0 - 5 + r;
        int gx = x0 - 5 + c;
        bool ok = ((unsigned)gy < 512u) && ((unsigned)gx < 512u);
        float pv = ok ? __ldg(pb + gy * 512 + gx) : 0.0f;
        float tv = ok ? __ldg(tb + gy * 512 + gx) : 0.0f;
        spt[r * SPW + c] = pack2(pv, tv);
    }
    __syncthreads();

    // ---- Phase 2: vertical conv, modulo-rotation windows ----
    // A+B fused (shared loads): tids 0-147, task = (col, 16-row half).
    // C (p*t scalar): tids 160-233, one full column each.
    if (tid < 148) {
        const int h = (tid >= 74);            // row half
        const int c = tid - h * 74;           // column
        const int rb = h * 16;                // first output row
        const u64* in = spt + c;
        u64 winA[11], winB[11];
        #pragma unroll
        for (int j = 0; j < 10; j++) {
            u64 v = in[(rb + j) * SPW];
            winA[j] = v;
            winB[j] = mul2(v, v);
        }
        u64* oA = vA + c * CS + rb;
        u64* oB = vB + c * CS + rb;
        #pragma unroll
        for (int r = 0; r < 16; r++) {
            u64 v = in[(rb + r + 10) * SPW];
            winA[(r + 10) % 11] = v;
            winB[(r + 10) % 11] = mul2(v, v);
            u64 a = mul2(pack2(GWc(0), GWc(0)), winA[r % 11]);
            u64 b = mul2(pack2(GWc(0), GWc(0)), winB[r % 11]);
            #pragma unroll
            for (int k = 1; k < 11; k++) {
                a = fma2(pack2(GWc(k), GWc(k)), winA[(r + k) % 11], a);
                b = fma2(pack2(GWc(k), GWc(k)), winB[(r + k) % 11], b);
            }
            oA[r] = a;
            oB[r] = b;
        }
    } else if (tid >= 160 && tid < 234) {
        const int c = tid - 160;
        const u64* in = spt + c;
        float win[11];
        #pragma unroll
        for (int j = 0; j < 10; j++) {
            float p, t; unpack2(in[j * SPW], p, t);
            win[j] = p * t;
        }
        float* oC = vC + c * CS;
        #pragma unroll
        for (int r = 0; r < 32; r++) {
            float p, t; unpack2(in[(r + 10) * SPW], p, t);
            win[(r + 10) % 11] = p * t;
            float a = GWc(0) * win[r % 11];
            #pragma unroll
            for (int k = 1; k < 11; k++) a = fmaf(GWc(k), win[(r + k) % 11], a);
            oC[r] = a;
        }
    }
    __syncthreads();

    // ---- Phase 3: horizontal conv + SSIM. warp = 32 rows, one x-group ----
    const int g = tid >> 5;     // x-group 0..7, outputs x = 8g..8g+7
    const int r = tid & 31;     // row

    u64 mu[8];
    {
        const u64* base = vA + (8 * g) * CS + r;
        u64 wv[18];
        #pragma unroll
        for (int j = 0; j < 18; j++) wv[j] = base[j * CS];
        #pragma unroll
        for (int o = 0; o < 8; o++) {
            u64 a = mul2(pack2(GWc(0), GWc(0)), wv[o]);
            #pragma unroll
            for (int k = 1; k < 11; k++)
                a = fma2(pack2(GWc(k), GWc(k)), wv[o + k], a);
            mu[o] = a;
        }
    }
    u64 sq[8];
    {
        const u64* base = vB + (8 * g) * CS + r;
        u64 wv[18];
        #pragma unroll
        for (int j = 0; j < 18; j++) wv[j] = base[j * CS];
        #pragma unroll
        for (int o = 0; o < 8; o++) {
            u64 a = mul2(pack2(GWc(0), GWc(0)), wv[o]);
            #pragma unroll
            for (int k = 1; k < 11; k++)
                a = fma2(pack2(GWc(k), GWc(k)), wv[o + k], a);
            sq[o] = a;
        }
    }
    float cpt[8];
    {
        const float* base = vC + (8 * g) * CS + r;
        float wc[18];
        #pragma unroll
        for (int j = 0; j < 18; j++) wc[j] = base[j * CS];
        u64 pw[14];
        #pragma unroll
        for (int j = 0; j < 14; j++) pw[j] = pack2(wc[j], wc[j + 4]);
        #pragma unroll
        for (int o = 0; o < 4; o++) {
            u64 a = mul2(pack2(GWc(0), GWc(0)), pw[o]);
            #pragma unroll
            for (int k = 1; k < 11; k++)
                a = fma2(pack2(GWc(k), GWc(k)), pw[o + k], a);
            unpack2(a, cpt[o], cpt[o + 4]);
        }
    }

    const float C1 = 0.0001f;
    const float C2 = 0.0009f;
    float lsum = 0.0f;
    #pragma unroll
    for (int o = 0; o < 8; o++) {
        float mu1, mu2, ep2, et2;
        unpack2(mu[o], mu1, mu2);
        unpack2(sq[o], ep2, et2);
        float mu1sq = mu1 * mu1;
        float mu2sq = mu2 * mu2;
        float mu12  = mu1 * mu2;
        float s1  = ep2 - mu1sq;
        float s2  = et2 - mu2sq;
        float s12 = cpt[o] - mu12;
        float num = (2.0f * mu12 + C1) * (2.0f * s12 + C2);
        float den = (mu1sq + mu2sq + C1) * (s1 + s2 + C2);
        lsum += __fdividef(num, den);
    }

    // ---- Deterministic block reduction ----
    #pragma unroll
    for (int off = 16; off > 0; off >>= 1)
        lsum += __shfl_down_sync(0xffffffffu, lsum, off);
    if ((tid & 31) == 0) sred[tid >> 5] = lsum;
    __syncthreads();

    __shared__ bool s_last;
    if (tid == 0) {
        float tot = 0.0f;
        #pragma unroll
        for (int wi = 0; wi < 8; wi++) tot += sred[wi];
        int bidx = (z * gridDim.y + blockIdx.y) * gridDim.x + blockIdx.x;
        g_partials[bidx] = tot;
        __threadfence();
        unsigned v = atomicAdd(&g_count, 1u);
        s_last = (v == (unsigned)(NBLK - 1));
    }
    __syncthreads();

    // ---- Last block finalizes (deterministic fixed-order sum) ----
    if (s_last) {
        __threadfence();
        double* dred = (double*)smem_raw;  // spt region is dead
        double s = 0.0;
        for (int i = tid; i < NBLK; i += 256)
            s += (double)g_partials[i];
        #pragma unroll
        for (int off = 16; off > 0; off >>= 1)
            s += __shfl_down_sync(0xffffffffu, s, off);
        if ((tid & 31) == 0) dred[tid >> 5] = s;
        __syncthreads();
        if (tid == 0) {
            double tot = 0.0;
            #pragma unroll
            for (int w = 0; w < 8; w++) tot += dred[w];
            out[0] = (float)(1.0 - tot / NTOT);
            g_count = 0;   // reset for next graph replay
        }
    }
}

extern "C" void kernel_launch(void* const* d_in, const int* in_sizes, int n_in,
                              void* d_out, int out_size)
{
    const float* pred = (const float*)d_in[0];
    const float* targ = (const float*)d_in[1];
    float* out = (float*)d_out;

    constexpr int smem_bytes =
        (LY * SPW + 2 * 74 * CS) * 8 + 74 * CS * 4 + 16 * 4;
    cudaFuncSetAttribute(ssim_tile_kernel,
                         cudaFuncAttributeMaxDynamicSharedMemorySize, smem_bytes);

    dim3 grid(GX, GY, GZ);
    ssim_tile_kernel<<<grid, 256, smem_bytes>>>(pred, targ, out);
}

// round 14
// speedup vs baseline: 1.0160x; 1.0160x over previous
#include <cuda_runtime.h>

// SSIM loss, pred/target [16,3,512,512] f32.
// Vertical-first separable 11-tap Gaussian, f32x2-packed:
//   stream A: (p, t) packed   stream B: (p*p, t*t) packed   stream C: p*t scalar
// Phase1: gmem -> smem (p,t) packed tile (74x42)
// Phase2: vertical conv, modulo-rotation register windows; A+B fused (shared
//         loads), tasks=(col,half) on tids 0-147; C on tids 160-233.
// Phase3: horizontal conv + SSIM map + deterministic block reduce
// Finalize folded into last-finished block (atomic counter, fixed-order sum).
// R14: occupancy 2 -> 3 blocks/SM (smem 72.4KB x3 = 217KB fits; regs 48K fits).

#define TX   64
#define TY   32
#define LX   74
#define LY   42
#define SPW  75      // input tile row stride (u64)
#define CS   33      // v* column stride (32 rows + 1 pad)
#define GX   (512/TX)
#define GY   (512/TY)
#define GZ   48
#define NBLK (GX*GY*GZ)
#define NTOT 12582912.0

using u64 = unsigned long long;

__host__ __device__ constexpr float GWc(int k) {
    return (k == 0) ? 0.00102838f
         : (k == 1) ? 0.00759875f
         : (k == 2) ? 0.03600077f
         : (k == 3) ? 0.10936070f
         : (k == 4) ? 0.21300553f
         : (k == 5) ? 0.26601172f
         : (k == 6) ? 0.21300553f
         : (k == 7) ? 0.10936070f
         : (k == 8) ? 0.03600077f
         : (k == 9) ? 0.00759875f
         :            0.00102838f;
}

__device__ __forceinline__ u64 pack2(float lo, float hi) {
    u64 r; asm("mov.b64 %0, {%1,%2};" : "=l"(r) : "f"(lo), "f"(hi)); return r;
}
__device__ __forceinline__ void unpack2(u64 v, float& lo, float& hi) {
    asm("mov.b64 {%0,%1}, %2;" : "=f"(lo), "=f"(hi) : "l"(v));
}
__device__ __forceinline__ u64 fma2(u64 a, u64 b, u64 c) {
    u64 r; asm("fma.rn.f32x2 %0, %1, %2, %3;" : "=l"(r) : "l"(a), "l"(b), "l"(c)); return r;
}
__device__ __forceinline__ u64 mul2(u64 a, u64 b) {
    u64 r; asm("mul.rn.f32x2 %0, %1, %2;" : "=l"(r) : "l"(a), "l"(b)); return r;
}

__device__ float g_partials[NBLK];
__device__ unsigned int g_count = 0;

__global__ void __launch_bounds__(256, 3)
ssim_tile_kernel(const float* __restrict__ pred, const float* __restrict__ targ,
                 float* __restrict__ out)
{
    extern __shared__ char smem_raw[];
    u64*   spt  = (u64*)smem_raw;              // LY*SPW   (p,t) tile
    u64*   vA   = spt + LY * SPW;              // 74*CS    vpass (mu1v, mu2v) [col][row]
    u64*   vB   = vA + 74 * CS;                // 74*CS    vpass (p2v, t2v)   [col][row]
    float* vC   = (float*)(vB + 74 * CS);      // 74*CS    vpass ptv          [col][row]
    float* sred = vC + 74 * CS;                // 8 floats

    const int tid = threadIdx.x;
    const int x0 = blockIdx.x * TX;
    const int y0 = blockIdx.y * TY;
    const int z  = blockIdx.z;
    const float* pb = pred + z * (512 * 512);
    const float* tb = targ + z * (512 * 512);

    // ---- Phase 1: load tile with halo, interleave (p,t) ----
    for (int i = tid; i < LY * LX; i += 256) {
        int r = i / LX;
        int c = i - r * LX;
        int gy = y0 - 5 + r;
        int gx = x0 - 5 + c;
        bool ok = ((unsigned)gy < 512u) && ((unsigned)gx < 512u);
        float pv = ok ? __ldg(pb + gy * 512 + gx) : 0.0f;
        float tv = ok ? __ldg(tb + gy * 512 + gx) : 0.0f;
        spt[r * SPW + c] = pack2(pv, tv);
    }
    __syncthreads();

    // ---- Phase 2: vertical conv, modulo-rotation windows ----
    // A+B fused (shared loads): tids 0-147, task = (col, 16-row half).
    // C (p*t scalar): tids 160-233, one full column each.
    if (tid < 148) {
        const int h = (tid >= 74);            // row half
        const int c = tid - h * 74;           // column
        const int rb = h * 16;                // first output row
        const u64* in = spt + c;
        u64 winA[11], winB[11];
        #pragma unroll
        for (int j = 0; j < 10; j++) {
            u64 v = in[(rb + j) * SPW];
            winA[j] = v;
            winB[j] = mul2(v, v);
        }
        u64* oA = vA + c * CS + rb;
        u64* oB = vB + c * CS + rb;
        #pragma unroll
        for (int r = 0; r < 16; r++) {
            u64 v = in[(rb + r + 10) * SPW];
            winA[(r + 10) % 11] = v;
            winB[(r + 10) % 11] = mul2(v, v);
            u64 a = mul2(pack2(GWc(0), GWc(0)), winA[r % 11]);
            u64 b = mul2(pack2(GWc(0), GWc(0)), winB[r % 11]);
            #pragma unroll
            for (int k = 1; k < 11; k++) {
                a = fma2(pack2(GWc(k), GWc(k)), winA[(r + k) % 11], a);
                b = fma2(pack2(GWc(k), GWc(k)), winB[(r + k) % 11], b);
            }
            oA[r] = a;
            oB[r] = b;
        }
    } else if (tid >= 160 && tid < 234) {
        const int c = tid - 160;
        const u64* in = spt + c;
        float win[11];
        #pragma unroll
        for (int j = 0; j < 10; j++) {
            float p, t; unpack2(in[j * SPW], p, t);
            win[j] = p * t;
        }
        float* oC = vC + c * CS;
        #pragma unroll
        for (int r = 0; r < 32; r++) {
            float p, t; unpack2(in[(r + 10) * SPW], p, t);
            win[(r + 10) % 11] = p * t;
            float a = GWc(0) * win[r % 11];
            #pragma unroll
            for (int k = 1; k < 11; k++) a = fmaf(GWc(k), win[(r + k) % 11], a);
            oC[r] = a;
        }
    }
    __syncthreads();

    // ---- Phase 3: horizontal conv + SSIM. warp = 32 rows, one x-group ----
    const int g = tid >> 5;     // x-group 0..7, outputs x = 8g..8g+7
    const int r = tid & 31;     // row

    u64 mu[8];
    {
        const u64* base = vA + (8 * g) * CS + r;
        u64 wv[18];
        #pragma unroll
        for (int j = 0; j < 18; j++) wv[j] = base[j * CS];
        #pragma unroll
        for (int o = 0; o < 8; o++) {
            u64 a = mul2(pack2(GWc(0), GWc(0)), wv[o]);
            #pragma unroll
            for (int k = 1; k < 11; k++)
                a = fma2(pack2(GWc(k), GWc(k)), wv[o + k], a);
            mu[o] = a;
        }
    }
    u64 sq[8];
    {
        const u64* base = vB + (8 * g) * CS + r;
        u64 wv[18];
        #pragma unroll
        for (int j = 0; j < 18; j++) wv[j] = base[j * CS];
        #pragma unroll
        for (int o = 0; o < 8; o++) {
            u64 a = mul2(pack2(GWc(0), GWc(0)), wv[o]);
            #pragma unroll
            for (int k = 1; k < 11; k++)
                a = fma2(pack2(GWc(k), GWc(k)), wv[o + k], a);
            sq[o] = a;
        }
    }
    float cpt[8];
    {
        const float* base = vC + (8 * g) * CS + r;
        float wc[18];
        #pragma unroll
        for (int j = 0; j < 18; j++) wc[j] = base[j * CS];
        u64 pw[14];
        #pragma unroll
        for (int j = 0; j < 14; j++) pw[j] = pack2(wc[j], wc[j + 4]);
        #pragma unroll
        for (int o = 0; o < 4; o++) {
            u64 a = mul2(pack2(GWc(0), GWc(0)), pw[o]);
            #pragma unroll
            for (int k = 1; k < 11; k++)
                a = fma2(pack2(GWc(k), GWc(k)), pw[o + k], a);
            unpack2(a, cpt[o], cpt[o + 4]);
        }
    }

    const float C1 = 0.0001f;
    const float C2 = 0.0009f;
    float lsum = 0.0f;
    #pragma unroll
    for (int o = 0; o < 8; o++) {
        float mu1, mu2, ep2, et2;
        unpack2(mu[o], mu1, mu2);
        unpack2(sq[o], ep2, et2);
        float mu1sq = mu1 * mu1;
        float mu2sq = mu2 * mu2;
        float mu12  = mu1 * mu2;
        float s1  = ep2 - mu1sq;
        float s2  = et2 - mu2sq;
        float s12 = cpt[o] - mu12;
        float num = (2.0f * mu12 + C1) * (2.0f * s12 + C2);
        float den = (mu1sq + mu2sq + C1) * (s1 + s2 + C2);
        lsum += __fdividef(num, den);
    }

    // ---- Deterministic block reduction ----
    #pragma unroll
    for (int off = 16; off > 0; off >>= 1)
        lsum += __shfl_down_sync(0xffffffffu, lsum, off);
    if ((tid & 31) == 0) sred[tid >> 5] = lsum;
    __syncthreads();

    __shared__ bool s_last;
    if (tid == 0) {
        float tot = 0.0f;
        #pragma unroll
        for (int wi = 0; wi < 8; wi++) tot += sred[wi];
        int bidx = (z * gridDim.y + blockIdx.y) * gridDim.x + blockIdx.x;
        g_partials[bidx] = tot;
        __threadfence();
        unsigned v = atomicAdd(&g_count, 1u);
        s_last = (v == (unsigned)(NBLK - 1));
    }
    __syncthreads();

    // ---- Last block finalizes (deterministic fixed-order sum) ----
    if (s_last) {
        __threadfence();
        double* dred = (double*)smem_raw;  // spt region is dead
        double s = 0.0;
        for (int i = tid; i < NBLK; i += 256)
            s += (double)g_partials[i];
        #pragma unroll
        for (int off = 16; off > 0; off >>= 1)
            s += __shfl_down_sync(0xffffffffu, s, off);
        if ((tid & 31) == 0) dred[tid >> 5] = s;
        __syncthreads();
        if (tid == 0) {
            double tot = 0.0;
            #pragma unroll
            for (int w = 0; w < 8; w++) tot += dred[w];
            out[0] = (float)(1.0 - tot / NTOT);
            g_count = 0;   // reset for next graph replay
        }
    }
}

extern "C" void kernel_launch(void* const* d_in, const int* in_sizes, int n_in,
                              void* d_out, int out_size)
{
    const float* pred = (const float*)d_in[0];
    const float* targ = (const float*)d_in[1];
    float* out = (float*)d_out;

    constexpr int smem_bytes =
        (LY * SPW + 2 * 74 * CS) * 8 + 74 * CS * 4 + 16 * 4;
    cudaFuncSetAttribute(ssim_tile_kernel,
                         cudaFuncAttributeMaxDynamicSharedMemorySize, smem_bytes);

    dim3 grid(GX, GY, GZ);
    ssim_tile_kernel<<<grid, 256, smem_bytes>>>(pred, targ, out);
}

// round 15
// speedup vs baseline: 1.1819x; 1.1633x over previous
#include <cuda_runtime.h>

// SSIM loss, pred/target [16,3,512,512] f32.
// Vertical-first separable 11-tap Gaussian.
// R15: one shared v-buffer reused across 3 stream rounds (A=(p,t) packed,
// B=(p2,t2) packed, C=p*t scalar) -> smem 74.1KB -> 45.1KB -> 4 blocks/SM.

#define TX   64
#define TY   32
#define LX   74
#define LY   42
#define SPW  75      // spt row stride (u64)
#define CS   33      // vbuf column stride, u64 view  (74*33*8  = 19536 B)
#define CSF  67      // vbuf column stride, f32 view  (74*67*4  = 19832 B)
#define VBYTES 19832
#define GX   (512/TX)
#define GY   (512/TY)
#define GZ   48
#define NBLK (GX*GY*GZ)
#define NTOT 12582912.0

using u64 = unsigned long long;

__host__ __device__ constexpr float GWc(int k) {
    return (k == 0) ? 0.00102838f
         : (k == 1) ? 0.00759875f
         : (k == 2) ? 0.03600077f
         : (k == 3) ? 0.10936070f
         : (k == 4) ? 0.21300553f
         : (k == 5) ? 0.26601172f
         : (k == 6) ? 0.21300553f
         : (k == 7) ? 0.10936070f
         : (k == 8) ? 0.03600077f
         : (k == 9) ? 0.00759875f
         :            0.00102838f;
}

__device__ __forceinline__ u64 pack2(float lo, float hi) {
    u64 r; asm("mov.b64 %0, {%1,%2};" : "=l"(r) : "f"(lo), "f"(hi)); return r;
}
__device__ __forceinline__ void unpack2(u64 v, float& lo, float& hi) {
    asm("mov.b64 {%0,%1}, %2;" : "=f"(lo), "=f"(hi) : "l"(v));
}
__device__ __forceinline__ u64 fma2(u64 a, u64 b, u64 c) {
    u64 r; asm("fma.rn.f32x2 %0, %1, %2, %3;" : "=l"(r) : "l"(a), "l"(b), "l"(c)); return r;
}
__device__ __forceinline__ u64 mul2(u64 a, u64 b) {
    u64 r; asm("mul.rn.f32x2 %0, %1, %2;" : "=l"(r) : "l"(a), "l"(b)); return r;
}

__device__ float g_partials[NBLK];
__device__ unsigned int g_count = 0;

__global__ void __launch_bounds__(256, 4)
ssim_tile_kernel(const float* __restrict__ pred, const float* __restrict__ targ,
                 float* __restrict__ out)
{
    extern __shared__ char smem_raw[];
    u64*   spt  = (u64*)smem_raw;                       // LY*SPW  (p,t) tile
    u64*   vb   = spt + LY * SPW;                       // shared v-buffer (u64 view)
    float* vbF  = (float*)vb;                           // f32 view for stream C
    float* sred = (float*)((char*)vb + VBYTES);        // 8 floats

    const int tid = threadIdx.x;
    const int x0 = blockIdx.x * TX;
    const int y0 = blockIdx.y * TY;
    const int z  = blockIdx.z;
    const float* pb = pred + z * (512 * 512);
    const float* tb = targ + z * (512 * 512);

    // ---- Phase 1: load tile with halo, interleave (p,t) ----
    for (int i = tid; i < LY * LX; i += 256) {
        int r = i / LX;
        int c = i - r * LX;
        int gy = y0 - 5 + r;
        int gx = x0 - 5 + c;
        bool ok = ((unsigned)gy < 512u) && ((unsigned)gx < 512u);
        float pv = ok ? __ldg(pb + gy * 512 + gx) : 0.0f;
        float tv = ok ? __ldg(tb + gy * 512 + gx) : 0.0f;
        spt[r * SPW + c] = pack2(pv, tv);
    }
    __syncthreads();

    // vpass task decode (tids 0-147): column c, 16-row half h
    const int vh  = (tid >= 74);
    const int vc  = tid - vh * 74;
    const int vrb = vh * 16;
    // hpass decode: x-group g (outputs 8g..8g+7), row r
    const int g = tid >> 5;
    const int r = tid & 31;

    // ================= Round A: (p, t) packed =================
    if (tid < 148) {
        const u64* in = spt + vrb * SPW + vc;
        u64 win[11];
        #pragma unroll
        for (int j = 0; j < 10; j++) win[j] = in[j * SPW];
        u64* o = vb + vc * CS + vrb;
        #pragma unroll
        for (int rr = 0; rr < 16; rr++) {
            win[(rr + 10) % 11] = in[(rr + 10) * SPW];
            u64 a = mul2(pack2(GWc(0), GWc(0)), win[rr % 11]);
            #pragma unroll
            for (int k = 1; k < 11; k++)
                a = fma2(pack2(GWc(k), GWc(k)), win[(rr + k) % 11], a);
            o[rr] = a;
        }
    }
    __syncthreads();

    u64 mu[8];
    {
        const u64* base = vb + (8 * g) * CS + r;
        u64 wv[18];
        #pragma unroll
        for (int j = 0; j < 18; j++) wv[j] = base[j * CS];
        #pragma unroll
        for (int o = 0; o < 8; o++) {
            u64 a = mul2(pack2(GWc(0), GWc(0)), wv[o]);
            #pragma unroll
            for (int k = 1; k < 11; k++)
                a = fma2(pack2(GWc(k), GWc(k)), wv[o + k], a);
            mu[o] = a;
        }
    }
    __syncthreads();

    // ================= Round B: (p*p, t*t) packed =================
    if (tid < 148) {
        const u64* in = spt + vrb * SPW + vc;
        u64 win[11];
        #pragma unroll
        for (int j = 0; j < 10; j++) { u64 v = in[j * SPW]; win[j] = mul2(v, v); }
        u64* o = vb + vc * CS + vrb;
        #pragma unroll
        for (int rr = 0; rr < 16; rr++) {
            u64 v = in[(rr + 10) * SPW];
            win[(rr + 10) % 11] = mul2(v, v);
            u64 a = mul2(pack2(GWc(0), GWc(0)), win[rr % 11]);
            #pragma unroll
            for (int k = 1; k < 11; k++)
                a = fma2(pack2(GWc(k), GWc(k)), win[(rr + k) % 11], a);
            o[rr] = a;
        }
    }
    __syncthreads();

    u64 sq[8];
    {
        const u64* base = vb + (8 * g) * CS + r;
        #pragma unroll
        for (int ch = 0; ch < 2; ch++) {      // chunked: cap register peak
            u64 wv[14];
            #pragma unroll
            for (int j = 0; j < 14; j++) wv[j] = base[(4 * ch + j) * CS];
            #pragma unroll
            for (int o = 0; o < 4; o++) {
                u64 a = mul2(pack2(GWc(0), GWc(0)), wv[o]);
                #pragma unroll
                for (int k = 1; k < 11; k++)
                    a = fma2(pack2(GWc(k), GWc(k)), wv[o + k], a);
                sq[4 * ch + o] = a;
            }
        }
    }
    __syncthreads();

    // ================= Round C: p*t scalar =================
    if (tid < 148) {
        const u64* in = spt + vrb * SPW + vc;
        float win[11];
        #pragma unroll
        for (int j = 0; j < 10; j++) {
            float p, t; unpack2(in[j * SPW], p, t);
            win[j] = p * t;
        }
        float* o = vbF + vc * CSF + vrb;
        #pragma unroll
        for (int rr = 0; rr < 16; rr++) {
            float p, t; unpack2(in[(rr + 10) * SPW], p, t);
            win[(rr + 10) % 11] = p * t;
            float a = GWc(0) * win[rr % 11];
            #pragma unroll
            for (int k = 1; k < 11; k++) a = fmaf(GWc(k), win[(rr + k) % 11], a);
            o[rr] = a;
        }
    }
    __syncthreads();

    float cpt[8];
    {
        const float* base = vbF + (8 * g) * CSF + r;
        float wc[18];
        #pragma unroll
        for (int j = 0; j < 18; j++) wc[j] = base[j * CSF];
        #pragma unroll
        for (int o = 0; o < 8; o++) {
            float a = GWc(0) * wc[o];
            #pragma unroll
            for (int k = 1; k < 11; k++) a = fmaf(GWc(k), wc[o + k], a);
            cpt[o] = a;
        }
    }

    // ================= SSIM map =================
    const float C1 = 0.0001f;
    const float C2 = 0.0009f;
    float lsum = 0.0f;
    #pragma unroll
    for (int o = 0; o < 8; o++) {
        float mu1, mu2, ep2, et2;
        unpack2(mu[o], mu1, mu2);
        unpack2(sq[o], ep2, et2);
        float mu1sq = mu1 * mu1;
        float mu2sq = mu2 * mu2;
        float mu12  = mu1 * mu2;
        float s1  = ep2 - mu1sq;
        float s2  = et2 - mu2sq;
        float s12 = cpt[o] - mu12;
        float num = (2.0f * mu12 + C1) * (2.0f * s12 + C2);
        float den = (mu1sq + mu2sq + C1) * (s1 + s2 + C2);
        lsum += __fdividef(num, den);
    }

    // ---- Deterministic block reduction ----
    #pragma unroll
    for (int off = 16; off > 0; off >>= 1)
        lsum += __shfl_down_sync(0xffffffffu, lsum, off);
    if ((tid & 31) == 0) sred[tid >> 5] = lsum;
    __syncthreads();

    __shared__ bool s_last;
    if (tid == 0) {
        float tot = 0.0f;
        #pragma unroll
        for (int wi = 0; wi < 8; wi++) tot += sred[wi];
        int bidx = (z * gridDim.y + blockIdx.y) * gridDim.x + blockIdx.x;
        g_partials[bidx] = tot;
        __threadfence();
        unsigned v = atomicAdd(&g_count, 1u);
        s_last = (v == (unsigned)(NBLK - 1));
    }
    __syncthreads();

    // ---- Last block finalizes (deterministic fixed-order sum) ----
    if (s_last) {
        __threadfence();
        double* dred = (double*)smem_raw;  // spt region is dead
        double s = 0.0;
        for (int i = tid; i < NBLK; i += 256)
            s += (double)g_partials[i];
        #pragma unroll
        for (int off = 16; off > 0; off >>= 1)
            s += __shfl_down_sync(0xffffffffu, s, off);
        if ((tid & 31) == 0) dred[tid >> 5] = s;
        __syncthreads();
        if (tid == 0) {
            double tot = 0.0;
            #pragma unroll
            for (int w = 0; w < 8; w++) tot += dred[w];
            out[0] = (float)(1.0 - tot / NTOT);
            g_count = 0;   // reset for next graph replay
        }
    }
}

extern "C" void kernel_launch(void* const* d_in, const int* in_sizes, int n_in,
                              void* d_out, int out_size)
{
    const float* pred = (const float*)d_in[0];
    const float* targ = (const float*)d_in[1];
    float* out = (float*)d_out;

    constexpr int smem_bytes = LY * SPW * 8 + VBYTES + 16 * 4;
    cudaFuncSetAttribute(ssim_tile_kernel,
                         cudaFuncAttributeMaxDynamicSharedMemorySize, smem_bytes);

    dim3 grid(GX, GY, GZ);
    ssim_tile_kernel<<<grid, 256, smem_bytes>>>(pred, targ, out);
}

// round 16
// speedup vs baseline: 1.3203x; 1.1171x over previous
#include <cuda_runtime.h>

// SSIM loss, pred/target [16,3,512,512] f32.
// Vertical-first separable 11-tap Gaussian.
// R15: one shared v-buffer reused across 3 stream rounds -> 45.1KB smem.
// R16: 5 blocks/SM (reg budget 48 via launch_bounds; all hpass rounds
//      chunked 2x4 outputs / 14-wide windows to cap live-register peak).

#define TX   64
#define TY   32
#define LX   74
#define LY   42
#define SPW  75      // spt row stride (u64)
#define CS   33      // vbuf column stride, u64 view  (74*33*8  = 19536 B)
#define CSF  67      // vbuf column stride, f32 view  (74*67*4  = 19832 B)
#define VBYTES 19832
#define GX   (512/TX)
#define GY   (512/TY)
#define GZ   48
#define NBLK (GX*GY*GZ)
#define NTOT 12582912.0

using u64 = unsigned long long;

__host__ __device__ constexpr float GWc(int k) {
    return (k == 0) ? 0.00102838f
         : (k == 1) ? 0.00759875f
         : (k == 2) ? 0.03600077f
         : (k == 3) ? 0.10936070f
         : (k == 4) ? 0.21300553f
         : (k == 5) ? 0.26601172f
         : (k == 6) ? 0.21300553f
         : (k == 7) ? 0.10936070f
         : (k == 8) ? 0.03600077f
         : (k == 9) ? 0.00759875f
         :            0.00102838f;
}

__device__ __forceinline__ u64 pack2(float lo, float hi) {
    u64 r; asm("mov.b64 %0, {%1,%2};" : "=l"(r) : "f"(lo), "f"(hi)); return r;
}
__device__ __forceinline__ void unpack2(u64 v, float& lo, float& hi) {
    asm("mov.b64 {%0,%1}, %2;" : "=f"(lo), "=f"(hi) : "l"(v));
}
__device__ __forceinline__ u64 fma2(u64 a, u64 b, u64 c) {
    u64 r; asm("fma.rn.f32x2 %0, %1, %2, %3;" : "=l"(r) : "l"(a), "l"(b), "l"(c)); return r;
}
__device__ __forceinline__ u64 mul2(u64 a, u64 b) {
    u64 r; asm("mul.rn.f32x2 %0, %1, %2;" : "=l"(r) : "l"(a), "l"(b)); return r;
}

__device__ float g_partials[NBLK];
__device__ unsigned int g_count = 0;

__global__ void __launch_bounds__(256, 5)
ssim_tile_kernel(const float* __restrict__ pred, const float* __restrict__ targ,
                 float* __restrict__ out)
{
    extern __shared__ char smem_raw[];
    u64*   spt  = (u64*)smem_raw;                       // LY*SPW  (p,t) tile
    u64*   vb   = spt + LY * SPW;                       // shared v-buffer (u64 view)
    float* vbF  = (float*)vb;                           // f32 view for stream C
    float* sred = (float*)((char*)vb + VBYTES);        // 8 floats

    const int tid = threadIdx.x;
    const int x0 = blockIdx.x * TX;
    const int y0 = blockIdx.y * TY;
    const int z  = blockIdx.z;
    const float* pb = pred + z * (512 * 512);
    const float* tb = targ + z * (512 * 512);

    // ---- Phase 1: load tile with halo, interleave (p,t) ----
    for (int i = tid; i < LY * LX; i += 256) {
        int r = i / LX;
        int c = i - r * LX;
        int gy = y0 - 5 + r;
        int gx = x0 - 5 + c;
        bool ok = ((unsigned)gy < 512u) && ((unsigned)gx < 512u);
        float pv = ok ? __ldg(pb + gy * 512 + gx) : 0.0f;
        float tv = ok ? __ldg(tb + gy * 512 + gx) : 0.0f;
        spt[r * SPW + c] = pack2(pv, tv);
    }
    __syncthreads();

    // vpass task decode (tids 0-147): column c, 16-row half h
    const int vh  = (tid >= 74);
    const int vc  = tid - vh * 74;
    const int vrb = vh * 16;
    // hpass decode: x-group g (outputs 8g..8g+7), row r
    const int g = tid >> 5;
    const int r = tid & 31;

    // ================= Round A: (p, t) packed =================
    if (tid < 148) {
        const u64* in = spt + vrb * SPW + vc;
        u64 win[11];
        #pragma unroll
        for (int j = 0; j < 10; j++) win[j] = in[j * SPW];
        u64* o = vb + vc * CS + vrb;
        #pragma unroll
        for (int rr = 0; rr < 16; rr++) {
            win[(rr + 10) % 11] = in[(rr + 10) * SPW];
            u64 a = mul2(pack2(GWc(0), GWc(0)), win[rr % 11]);
            #pragma unroll
            for (int k = 1; k < 11; k++)
                a = fma2(pack2(GWc(k), GWc(k)), win[(rr + k) % 11], a);
            o[rr] = a;
        }
    }
    __syncthreads();

    u64 mu[8];
    {
        const u64* base = vb + (8 * g) * CS + r;
        #pragma unroll
        for (int ch = 0; ch < 2; ch++) {      // chunked: cap register peak
            u64 wv[14];
            #pragma unroll
            for (int j = 0; j < 14; j++) wv[j] = base[(4 * ch + j) * CS];
            #pragma unroll
            for (int o = 0; o < 4; o++) {
                u64 a = mul2(pack2(GWc(0), GWc(0)), wv[o]);
                #pragma unroll
                for (int k = 1; k < 11; k++)
                    a = fma2(pack2(GWc(k), GWc(k)), wv[o + k], a);
                mu[4 * ch + o] = a;
            }
        }
    }
    __syncthreads();

    // ================= Round B: (p*p, t*t) packed =================
    if (tid < 148) {
        const u64* in = spt + vrb * SPW + vc;
        u64 win[11];
        #pragma unroll
        for (int j = 0; j < 10; j++) { u64 v = in[j * SPW]; win[j] = mul2(v, v); }
        u64* o = vb + vc * CS + vrb;
        #pragma unroll
        for (int rr = 0; rr < 16; rr++) {
            u64 v = in[(rr + 10) * SPW];
            win[(rr + 10) % 11] = mul2(v, v);
            u64 a = mul2(pack2(GWc(0), GWc(0)), win[rr % 11]);
            #pragma unroll
            for (int k = 1; k < 11; k++)
                a = fma2(pack2(GWc(k), GWc(k)), win[(rr + k) % 11], a);
            o[rr] = a;
        }
    }
    __syncthreads();

    u64 sq[8];
    {
        const u64* base = vb + (8 * g) * CS + r;
        #pragma unroll
        for (int ch = 0; ch < 2; ch++) {
            u64 wv[14];
            #pragma unroll
            for (int j = 0; j < 14; j++) wv[j] = base[(4 * ch + j) * CS];
            #pragma unroll
            for (int o = 0; o < 4; o++) {
                u64 a = mul2(pack2(GWc(0), GWc(0)), wv[o]);
                #pragma unroll
                for (int k = 1; k < 11; k++)
                    a = fma2(pack2(GWc(k), GWc(k)), wv[o + k], a);
                sq[4 * ch + o] = a;
            }
        }
    }
    __syncthreads();

    // ================= Round C: p*t scalar =================
    if (tid < 148) {
        const u64* in = spt + vrb * SPW + vc;
        float win[11];
        #pragma unroll
        for (int j = 0; j < 10; j++) {
            float p, t; unpack2(in[j * SPW], p, t);
            win[j] = p * t;
        }
        float* o = vbF + vc * CSF + vrb;
        #pragma unroll
        for (int rr = 0; rr < 16; rr++) {
            float p, t; unpack2(in[(rr + 10) * SPW], p, t);
            win[(rr + 10) % 11] = p * t;
            float a = GWc(0) * win[rr % 11];
            #pragma unroll
            for (int k = 1; k < 11; k++) a = fmaf(GWc(k), win[(rr + k) % 11], a);
            o[rr] = a;
        }
    }
    __syncthreads();

    float cpt[8];
    {
        const float* base = vbF + (8 * g) * CSF + r;
        #pragma unroll
        for (int ch = 0; ch < 2; ch++) {
            float wc[14];
            #pragma unroll
            for (int j = 0; j < 14; j++) wc[j] = base[(4 * ch + j) * CSF];
            #pragma unroll
            for (int o = 0; o < 4; o++) {
                float a = GWc(0) * wc[o];
                #pragma unroll
                for (int k = 1; k < 11; k++) a = fmaf(GWc(k), wc[o + k], a);
                cpt[4 * ch + o] = a;
            }
        }
    }

    // ================= SSIM map =================
    const float C1 = 0.0001f;
    const float C2 = 0.0009f;
    float lsum = 0.0f;
    #pragma unroll
    for (int o = 0; o < 8; o++) {
        float mu1, mu2, ep2, et2;
        unpack2(mu[o], mu1, mu2);
        unpack2(sq[o], ep2, et2);
        float mu1sq = mu1 * mu1;
        float mu2sq = mu2 * mu2;
        float mu12  = mu1 * mu2;
        float s1  = ep2 - mu1sq;
        float s2  = et2 - mu2sq;
        float s12 = cpt[o] - mu12;
        float num = (2.0f * mu12 + C1) * (2.0f * s12 + C2);
        float den = (mu1sq + mu2sq + C1) * (s1 + s2 + C2);
        lsum += __fdividef(num, den);
    }

    // ---- Deterministic block reduction ----
    #pragma unroll
    for (int off = 16; off > 0; off >>= 1)
        lsum += __shfl_down_sync(0xffffffffu, lsum, off);
    if ((tid & 31) == 0) sred[tid >> 5] = lsum;
    __syncthreads();

    __shared__ bool s_last;
    if (tid == 0) {
        float tot = 0.0f;
        #pragma unroll
        for (int wi = 0; wi < 8; wi++) tot += sred[wi];
        int bidx = (z * gridDim.y + blockIdx.y) * gridDim.x + blockIdx.x;
        g_partials[bidx] = tot;
        __threadfence();
        unsigned v = atomicAdd(&g_count, 1u);
        s_last = (v == (unsigned)(NBLK - 1));
    }
    __syncthreads();

    // ---- Last block finalizes (deterministic fixed-order sum) ----
    if (s_last) {
        __threadfence();
        double* dred = (double*)smem_raw;  // spt region is dead
        double s = 0.0;
        for (int i = tid; i < NBLK; i += 256)
            s += (double)g_partials[i];
        #pragma unroll
        for (int off = 16; off > 0; off >>= 1)
            s += __shfl_down_sync(0xffffffffu, s, off);
        if ((tid & 31) == 0) dred[tid >> 5] = s;
        __syncthreads();
        if (tid == 0) {
            double tot = 0.0;
            #pragma unroll
            for (int w = 0; w < 8; w++) tot += dred[w];
            out[0] = (float)(1.0 - tot / NTOT);
            g_count = 0;   // reset for next graph replay
        }
    }
}

extern "C" void kernel_launch(void* const* d_in, const int* in_sizes, int n_in,
                              void* d_out, int out_size)
{
    const float* pred = (const float*)d_in[0];
    const float* targ = (const float*)d_in[1];
    float* out = (float*)d_out;

    constexpr int smem_bytes = LY * SPW * 8 + VBYTES + 16 * 4;
    cudaFuncSetAttribute(ssim_tile_kernel,
                         cudaFuncAttributeMaxDynamicSharedMemorySize, smem_bytes);

    dim3 grid(GX, GY, GZ);
    ssim_tile_kernel<<<grid, 256, smem_bytes>>>(pred, targ, out);
}